// round 7
// baseline (speedup 1.0000x reference)
#include <cuda_runtime.h>
#include <math.h>

// Problem constants: generated [2, 3, 96, 96]
#define B       2
#define NPIX    9216            // 96*96
#define TOTQ    (B * NPIX)      // 18432 queries
#define K       8               // NUM_CLUSTERS
#define NTHR    256
#define QPT     4               // queries per thread
#define QPB     (NTHR * QPT)    // 1024 queries per CTA
#define NQG     (NPIX / QPB)    // 9 query groups per batch

// Phase 1: threshold from a uniform 1/8 sample (stride 8), 16 subchunks
#define SSTRIDE 8
#define NSC     16
#define SSZ     (NPIX / SSTRIDE / NSC)  // 72 samples per subchunk
#define BOOT    24                      // exact unconditional bootstrap

// Phase 2: full scan in 16 chunks
#define NCHUNK  16
#define CHUNK   (NPIX / NCHUNK)         // 576

// survivor buffers: flush threshold 4 entries, capacity 8 (4 slack for the
// once-per-4-iterations flush check; growth <= 1/iter/buffer)
#define FT      4
#define CAPP    8
#define FTN     (FT * NTHR)

#define NMERGE  (TOTQ / NTHR)           // 72 merge blocks

// Device scratch (allocation-free rule: __device__ globals)
__device__ float4 g_cand[B * NPIX];            // {-2x,-2y,-2z,|c|^2}
__device__ float  g_tpart[NSC * K][TOTQ];      // phase-1 partial top-8 (scores)
__device__ float  g_thr[TOTQ];                 // per-query threshold (scores)
__device__ float  g_part[NCHUNK * K][TOTQ];    // phase-2 partial top-8 (d^2)
__device__ float  g_bsum[NMERGE];
__device__ unsigned g_ticket;                  // zero-init; reset after use

// Scalar compare-exchange insert into sorted-ascending t[0..K-1].
__device__ __forceinline__ void insert8s(float (&t)[K], float u) {
    #pragma unroll
    for (int k = 0; k < K; k++) {
        float lo = fminf(t[k], u);
        u = fmaxf(t[k], u);
        t[k] = lo;
    }
}

// Drain survivor buffer [tid, idx) stride NTHR into the CE network.
__device__ __forceinline__ void drain(const float* buf, int tid, int& idx,
                                      float (&t)[K], float& m) {
    for (int i = tid; i < idx; i += NTHR) {
        float v = buf[i];
        if (v < m) { insert8s(t, v); m = t[K - 1]; }
    }
    idx = tid;
}

// ---------------------------------------------------------------------------
// Kernel 1: pack candidates as float4 {-2x,-2y,-2z,|c|^2}
// ---------------------------------------------------------------------------
__global__ void prep_kernel(const float* __restrict__ in) {
    int idx = blockIdx.x * blockDim.x + threadIdx.x;   // [0, TOTQ)
    if (idx >= TOTQ) return;
    int b = idx / NPIX;
    int i = idx - b * NPIX;
    const float* base = in + (size_t)b * 3 * NPIX;
    float x = base[i];
    float y = base[NPIX + i];
    float z = base[2 * NPIX + i];
    g_cand[idx] = make_float4(-2.0f * x, -2.0f * y, -2.0f * z,
                              x * x + y * y + z * z);
}

// ---------------------------------------------------------------------------
// Kernel 2 (phase 1): exact top-8 over a strided sample subchunk.
// Bootstrap = 24 unconditional CE inserts; remainder buffered vs live t[7].
// ---------------------------------------------------------------------------
__global__ void __launch_bounds__(NTHR)
thresh_topk(const float* __restrict__ in) {
    __shared__ float4 sh[SSZ];                     // 1152 B
    __shared__ float  sbuf[QPT * CAPP * NTHR];     // 32768 B

    int bid = blockIdx.x;                // [0, 288)
    int sc  = bid & (NSC - 1);
    int qg  = (bid >> 4) % NQG;
    int b   = bid / (NQG * NSC);

    int tid = threadIdx.x;
    for (int i = tid; i < SSZ; i += NTHR)
        sh[i] = g_cand[b * NPIX + (sc * SSZ + i) * SSTRIDE];

    int q0 = qg * QPB + tid;
    const float* base = in + (size_t)b * 3 * NPIX;
    float ax[QPT], ay[QPT], az[QPT];
    #pragma unroll
    for (int r = 0; r < QPT; r++) {
        int q = q0 + r * NTHR;
        ax[r] = base[q]; ay[r] = base[NPIX + q]; az[r] = base[2 * NPIX + q];
    }

    float t0[K], t1[K], t2[K], t3[K];
    #pragma unroll
    for (int k = 0; k < K; k++) { t0[k]=3e30f; t1[k]=3e30f; t2[k]=3e30f; t3[k]=3e30f; }

    __syncthreads();

    // exact bootstrap over first BOOT samples
    for (int j = 0; j < BOOT; j++) {
        float4 cv = sh[j];
        insert8s(t0, fmaf(ax[0],cv.x, fmaf(ay[0],cv.y, fmaf(az[0],cv.z, cv.w))));
        insert8s(t1, fmaf(ax[1],cv.x, fmaf(ay[1],cv.y, fmaf(az[1],cv.z, cv.w))));
        insert8s(t2, fmaf(ax[2],cv.x, fmaf(ay[2],cv.y, fmaf(az[2],cv.z, cv.w))));
        insert8s(t3, fmaf(ax[3],cv.x, fmaf(ay[3],cv.y, fmaf(az[3],cv.z, cv.w))));
    }
    float m0 = t0[K-1], m1 = t1[K-1], m2 = t2[K-1], m3 = t3[K-1];

    float* buf0 = sbuf;
    float* buf1 = sbuf + CAPP * NTHR;
    float* buf2 = sbuf + 2 * CAPP * NTHR;
    float* buf3 = sbuf + 3 * CAPP * NTHR;
    int i0 = tid, i1 = tid, i2 = tid, i3 = tid;

    for (int j4 = BOOT; j4 < SSZ; j4 += 4) {
        #pragma unroll
        for (int u = 0; u < 4; u++) {
            float4 cv = sh[j4 + u];
            float d0 = fmaf(ax[0],cv.x, fmaf(ay[0],cv.y, fmaf(az[0],cv.z, cv.w)));
            float d1 = fmaf(ax[1],cv.x, fmaf(ay[1],cv.y, fmaf(az[1],cv.z, cv.w)));
            float d2 = fmaf(ax[2],cv.x, fmaf(ay[2],cv.y, fmaf(az[2],cv.z, cv.w)));
            float d3 = fmaf(ax[3],cv.x, fmaf(ay[3],cv.y, fmaf(az[3],cv.z, cv.w)));
            buf0[i0] = d0; i0 += (d0 < m0) ? NTHR : 0;
            buf1[i1] = d1; i1 += (d1 < m1) ? NTHR : 0;
            buf2[i2] = d2; i2 += (d2 < m2) ? NTHR : 0;
            buf3[i3] = d3; i3 += (d3 < m3) ? NTHR : 0;
        }
        if (i0 >= FTN || i1 >= FTN || i2 >= FTN || i3 >= FTN) {
            drain(buf0, tid, i0, t0, m0);
            drain(buf1, tid, i1, t1, m1);
            drain(buf2, tid, i2, t2, m2);
            drain(buf3, tid, i3, t3, m3);
        }
    }
    drain(buf0, tid, i0, t0, m0);
    drain(buf1, tid, i1, t1, m1);
    drain(buf2, tid, i2, t2, m2);
    drain(buf3, tid, i3, t3, m3);

    int gq = b * NPIX + q0;
    #pragma unroll
    for (int k = 0; k < K; k++) {
        g_tpart[sc * K + k][gq]            = t0[k];
        g_tpart[sc * K + k][gq + NTHR]     = t1[k];
        g_tpart[sc * K + k][gq + 2*NTHR]   = t2[k];
        g_tpart[sc * K + k][gq + 3*NTHR]   = t3[k];
    }
}

// ---------------------------------------------------------------------------
// Kernel 3 (phase 1.5): merge NSC score partials -> per-query threshold
// ---------------------------------------------------------------------------
__global__ void __launch_bounds__(NTHR)
thresh_merge() {
    int q = blockIdx.x * blockDim.x + threadIdx.x;   // [0, TOTQ)
    float t[K];
    #pragma unroll
    for (int k = 0; k < K; k++) t[k] = 3.0e30f;
    #pragma unroll 8
    for (int j = 0; j < NSC * K; j++) {
        float u = g_tpart[j][q];
        if (u < t[K - 1]) insert8s(t, u);
    }
    // strict-< gate downstream must admit d == T  ->  open the bound one ulp
    g_thr[q] = nextafterf(t[K - 1], 3.4e38f);
}

// ---------------------------------------------------------------------------
// Kernel 4 (phase 2): full chunked scan, 4 queries/thread, survivor-buffered
// selection with top-8 state initialized at the per-query threshold.
// ---------------------------------------------------------------------------
__global__ void __launch_bounds__(NTHR)
topk_kernel(const float* __restrict__ in) {
    __shared__ float4 sh[CHUNK];                   // 9216 B
    __shared__ float  sbuf[QPT * CAPP * NTHR];     // 32768 B

    int bid = blockIdx.x;                // [0, 288)
    int c   = bid & (NCHUNK - 1);
    int qg  = (bid >> 4) % NQG;
    int b   = bid / (NQG * NCHUNK);

    int tid = threadIdx.x;
    for (int i = tid; i < CHUNK; i += NTHR)
        sh[i] = g_cand[b * NPIX + c * CHUNK + i];

    int q0 = qg * QPB + tid;
    int gq = b * NPIX + q0;
    const float* base = in + (size_t)b * 3 * NPIX;
    float ax[QPT], ay[QPT], az[QPT];
    #pragma unroll
    for (int r = 0; r < QPT; r++) {
        int q = q0 + r * NTHR;
        ax[r] = base[q]; ay[r] = base[NPIX + q]; az[r] = base[2 * NPIX + q];
    }

    float m0 = g_thr[gq];
    float m1 = g_thr[gq + NTHR];
    float m2 = g_thr[gq + 2 * NTHR];
    float m3 = g_thr[gq + 3 * NTHR];
    float t0[K], t1[K], t2[K], t3[K];
    #pragma unroll
    for (int k = 0; k < K; k++) { t0[k]=m0; t1[k]=m1; t2[k]=m2; t3[k]=m3; }

    __syncthreads();

    float* buf0 = sbuf;
    float* buf1 = sbuf + CAPP * NTHR;
    float* buf2 = sbuf + 2 * CAPP * NTHR;
    float* buf3 = sbuf + 3 * CAPP * NTHR;
    int i0 = tid, i1 = tid, i2 = tid, i3 = tid;

    for (int j4 = 0; j4 < CHUNK; j4 += 4) {
        #pragma unroll
        for (int u = 0; u < 4; u++) {
            float4 cv = sh[j4 + u];
            float d0 = fmaf(ax[0],cv.x, fmaf(ay[0],cv.y, fmaf(az[0],cv.z, cv.w)));
            float d1 = fmaf(ax[1],cv.x, fmaf(ay[1],cv.y, fmaf(az[1],cv.z, cv.w)));
            float d2 = fmaf(ax[2],cv.x, fmaf(ay[2],cv.y, fmaf(az[2],cv.z, cv.w)));
            float d3 = fmaf(ax[3],cv.x, fmaf(ay[3],cv.y, fmaf(az[3],cv.z, cv.w)));
            buf0[i0] = d0; i0 += (d0 < m0) ? NTHR : 0;   // unconditional store,
            buf1[i1] = d1; i1 += (d1 < m1) ? NTHR : 0;   // predicated bump
            buf2[i2] = d2; i2 += (d2 < m2) ? NTHR : 0;
            buf3[i3] = d3; i3 += (d3 < m3) ? NTHR : 0;
        }
        if (i0 >= FTN || i1 >= FTN || i2 >= FTN || i3 >= FTN) {
            drain(buf0, tid, i0, t0, m0);
            drain(buf1, tid, i1, t1, m1);
            drain(buf2, tid, i2, t2, m2);
            drain(buf3, tid, i3, t3, m3);
        }
    }
    drain(buf0, tid, i0, t0, m0);
    drain(buf1, tid, i1, t1, m1);
    drain(buf2, tid, i2, t2, m2);
    drain(buf3, tid, i3, t3, m3);

    #pragma unroll
    for (int r = 0; r < QPT; r++) {
        float q2 = fmaf(ax[r], ax[r], fmaf(ay[r], ay[r], az[r] * az[r]));
        float* t = (r == 0) ? t0 : (r == 1) ? t1 : (r == 2) ? t2 : t3;
        #pragma unroll
        for (int k = 0; k < K; k++)
            g_part[c * K + k][gq + r * NTHR] = t[k] + q2;   // coalesced
    }
}

// ---------------------------------------------------------------------------
// Kernel 5: merge NCHUNK partials -> per-query sum of sqrt d; fused final
// reduction via last-block ticket. Smallest element = self distance -> drop.
// ---------------------------------------------------------------------------
__global__ void __launch_bounds__(NTHR)
merge_reduce(float* __restrict__ out) {
    __shared__ float red[NTHR];
    __shared__ int islast;
    int q = blockIdx.x * NTHR + threadIdx.x;   // [0, TOTQ)

    float t[K];
    #pragma unroll
    for (int k = 0; k < K; k++) t[k] = 3.0e30f;

    #pragma unroll 8
    for (int j = 0; j < NCHUNK * K; j++) {
        float v = g_part[j][q];
        if (v < t[K - 1]) insert8s(t, v);
    }

    // t[0] is the self-distance (reference value: exactly 0) -> contribute 0.
    float s = 0.0f;
    #pragma unroll
    for (int k = 1; k < K; k++) s += sqrtf(fmaxf(t[k], 0.0f));

    red[threadIdx.x] = s;
    __syncthreads();
    #pragma unroll
    for (int w = NTHR / 2; w > 0; w >>= 1) {
        if (threadIdx.x < w) red[threadIdx.x] += red[threadIdx.x + w];
        __syncthreads();
    }
    if (threadIdx.x == 0) {
        g_bsum[blockIdx.x] = red[0];
        __threadfence();
        unsigned r = atomicAdd(&g_ticket, 1u);
        islast = (r == (unsigned)(gridDim.x - 1));
    }
    __syncthreads();

    if (islast) {
        float v = (threadIdx.x < NMERGE) ? __ldcg(&g_bsum[threadIdx.x]) : 0.0f;
        red[threadIdx.x] = v;
        __syncthreads();
        #pragma unroll
        for (int w = NTHR / 2; w > 0; w >>= 1) {
            if (threadIdx.x < w) red[threadIdx.x] += red[threadIdx.x + w];
            __syncthreads();
        }
        if (threadIdx.x == 0) {
            out[0] = -red[0] / (float)(TOTQ * K);
            g_ticket = 0;    // reset for next graph replay
        }
    }
}

extern "C" void kernel_launch(void* const* d_in, const int* in_sizes, int n_in,
                              void* d_out, int out_size) {
    const float* in = (const float*)d_in[0];
    float* out = (float*)d_out;

    prep_kernel<<<(TOTQ + NTHR - 1) / NTHR, NTHR>>>(in);
    thresh_topk<<<B * NQG * NSC, NTHR>>>(in);
    thresh_merge<<<TOTQ / NTHR, NTHR>>>();
    topk_kernel<<<B * NQG * NCHUNK, NTHR>>>(in);
    merge_reduce<<<NMERGE, NTHR>>>(out);
}